// round 4
// baseline (speedup 1.0000x reference)
#include <cuda_runtime.h>
#include <cuda_bf16.h>

#define NN 100000
#define NE 1600000
#define D  64

// ---------------- scratch (static device globals; no allocation) -------------
__device__ int   g_deg[NN];
__device__ int   g_fill[NN];
__device__ int   g_rowptr[NN + 1];
__device__ int   g_bsum[128];
__device__ int   g_col[NE];
__device__ float g_h[NN * D];
__device__ float g_agg[NN * D];
__device__ int   g_is64;

// ---------------- edge_index dtype detection ---------------------------------
// int64 little-endian with values in [0,NN): every odd int32 word is 0.
// int32 data: odd words are random node ids (all-zero prob ~ 1e-320).
__global__ void k_detect(const int* __restrict__ w) {
    if (threadIdx.x == 0 && blockIdx.x == 0) {
        int is64 = 1;
        for (int i = 0; i < 64; i++)
            if (w[2 * i + 1] != 0) { is64 = 0; break; }
        g_is64 = is64;
    }
}

__device__ __forceinline__ int edge_at(const void* ei, long long idx) {
    if (g_is64) return (int)((const long long*)ei)[idx];
    return ((const int*)ei)[idx];
}

// ---------------- CSR construction ------------------------------------------
__global__ void k_zero() {
    int i = blockIdx.x * blockDim.x + threadIdx.x;
    if (i < NN) { g_deg[i] = 0; g_fill[i] = 0; }
}

__global__ void k_deg(const void* __restrict__ ei) {
    int e = blockIdx.x * blockDim.x + threadIdx.x;
    if (e >= NE) return;
    int d = edge_at(ei, (long long)NE + e);
    if ((unsigned)d < NN) atomicAdd(&g_deg[d], 1);
}

// block-level inclusive scan (1024 elems/block), exclusive result to rowptr
__global__ void k_scan1() {
    __shared__ int sh[1024];
    int t = threadIdx.x;
    int i = blockIdx.x * 1024 + t;
    int v = (i < NN) ? g_deg[i] : 0;
    sh[t] = v;
    __syncthreads();
    #pragma unroll
    for (int off = 1; off < 1024; off <<= 1) {
        int add = (t >= off) ? sh[t - off] : 0;
        __syncthreads();
        sh[t] += add;
        __syncthreads();
    }
    if (i < NN) g_rowptr[i] = sh[t] - v;      // exclusive within block
    if (t == 1023) g_bsum[blockIdx.x] = sh[1023];
}

__global__ void k_scan2(int nblocks) {
    int running = 0;
    for (int b = 0; b < nblocks; b++) {
        int t = g_bsum[b];
        g_bsum[b] = running;
        running += t;
    }
    g_rowptr[NN] = running;   // == NE
}

__global__ void k_scan3() {
    int i = blockIdx.x * blockDim.x + threadIdx.x;
    if (i < NN) g_rowptr[i] += g_bsum[i >> 10];
}

__global__ void k_fill(const void* __restrict__ ei) {
    int e = blockIdx.x * blockDim.x + threadIdx.x;
    if (e >= NE) return;
    int s = edge_at(ei, e);
    int d = edge_at(ei, (long long)NE + e);
    if ((unsigned)d >= NN || (unsigned)s >= NN) return;
    int pos = g_rowptr[d] + atomicAdd(&g_fill[d], 1);
    g_col[pos] = s;
}

// ---------------- mean aggregation: warp per node ----------------------------
__global__ void k_agg(const float* __restrict__ hin) {
    int node = blockIdx.x * 8 + (threadIdx.x >> 5);
    if (node >= NN) return;
    int lane = threadIdx.x & 31;
    int beg = g_rowptr[node], end = g_rowptr[node + 1];
    float s0 = 0.f, s1 = 0.f;
    for (int e = beg; e < end; e++) {
        const float* r = hin + (size_t)g_col[e] * D;
        s0 += r[lane];
        s1 += r[lane + 32];
    }
    float inv = 1.0f / (float)max(end - beg, 1);
    g_agg[node * D + lane]      = s0 * inv;
    g_agg[node * D + 32 + lane] = s1 * inv;
}

// ---------------- fused dual GEMM + bias + leaky relu ------------------------
// block = 128 threads, 128 nodes; weights transposed in smem (pad 68, 16B rows)
#define WPAD 68
#define RPAD 65
#define SH_FLOATS (2 * 64 * WPAD + 2 * 128 * RPAD)

__global__ void k_linear(const float* __restrict__ hin,
                         const float* __restrict__ Wl,
                         const float* __restrict__ bl,
                         const float* __restrict__ Wr,
                         float* __restrict__ hout) {
    extern __shared__ float sh[];
    float* sWl = sh;                       // [64][WPAD], sWl[k*WPAD+d] = Wl[d][k]
    float* sWr = sh + 64 * WPAD;
    float* sM  = sh + 2 * 64 * WPAD;       // [128][RPAD]
    float* sH  = sM + 128 * RPAD;
    __shared__ float sB[64];

    int tid = threadIdx.x;

    for (int i = tid; i < 4096; i += 128) {
        int d = i >> 6, k = i & 63;
        sWl[k * WPAD + d] = Wl[i];
        sWr[k * WPAD + d] = Wr[i];
    }
    if (tid < 64) sB[tid] = bl[tid];

    int base = blockIdx.x * 128 * D;
    for (int i = tid; i < 128 * D; i += 128) {
        int idx = base + i;
        float m = 0.f, hv = 0.f;
        if (idx < NN * D) { m = g_agg[idx]; hv = hin[idx]; }
        int nn = i >> 6, k = i & 63;
        sM[nn * RPAD + k] = m;
        sH[nn * RPAD + k] = hv;
    }
    __syncthreads();

    float acc[64];
    #pragma unroll
    for (int d = 0; d < 64; d++) acc[d] = sB[d];

    for (int k = 0; k < 64; k++) {
        float m  = sM[tid * RPAD + k];
        float hv = sH[tid * RPAD + k];
        const float4* wl4 = reinterpret_cast<const float4*>(sWl + k * WPAD);
        const float4* wr4 = reinterpret_cast<const float4*>(sWr + k * WPAD);
        #pragma unroll
        for (int d4 = 0; d4 < 16; d4++) {
            float4 a = wl4[d4];
            float4 b = wr4[d4];
            acc[d4 * 4 + 0] += m * a.x + hv * b.x;
            acc[d4 * 4 + 1] += m * a.y + hv * b.y;
            acc[d4 * 4 + 2] += m * a.z + hv * b.z;
            acc[d4 * 4 + 3] += m * a.w + hv * b.w;
        }
    }
    __syncthreads();

    // leaky relu + transpose through smem for coalesced store
    #pragma unroll
    for (int d = 0; d < 64; d++) {
        float v = acc[d];
        sM[tid * RPAD + d] = (v >= 0.f) ? v : 0.01f * v;
    }
    __syncthreads();
    for (int i = tid; i < 128 * D; i += 128) {
        int idx = base + i;
        if (idx < NN * D) hout[idx] = sM[(i >> 6) * RPAD + (i & 63)];
    }
}

// ---------------- output head: warp per node ---------------------------------
__global__ void k_out(const float* __restrict__ h,
                      const float* __restrict__ Wout,
                      const float* __restrict__ bout,
                      float* __restrict__ out) {
    int node = blockIdx.x * 8 + (threadIdx.x >> 5);
    if (node >= NN) return;
    int lane = threadIdx.x & 31;
    float v = h[node * D + lane] * Wout[lane]
            + h[node * D + 32 + lane] * Wout[32 + lane];
    #pragma unroll
    for (int off = 16; off; off >>= 1) v += __shfl_down_sync(0xffffffff, v, off);
    if (lane == 0) out[node] = v + bout[0];
}

// ---------------- launch ------------------------------------------------------
extern "C" void kernel_launch(void* const* d_in, const int* in_sizes, int n_in,
                              void* d_out, int out_size) {
    const void*      ei   = d_in[1];
    const float*     x    = (const float*)d_in[0];
    const float*     Wl1  = (const float*)d_in[2];
    const float*     bl1  = (const float*)d_in[3];
    const float*     Wr1  = (const float*)d_in[4];
    const float*     Wl2  = (const float*)d_in[5];
    const float*     bl2  = (const float*)d_in[6];
    const float*     Wr2  = (const float*)d_in[7];
    const float*     Wl3  = (const float*)d_in[8];
    const float*     bl3  = (const float*)d_in[9];
    const float*     Wr3  = (const float*)d_in[10];
    const float*     Wout = (const float*)d_in[11];
    const float*     bout = (const float*)d_in[12];
    float* out = (float*)d_out;

    static bool attr_set = false;
    if (!attr_set) {
        cudaFuncSetAttribute(k_linear, cudaFuncAttributeMaxDynamicSharedMemorySize,
                             SH_FLOATS * (int)sizeof(float));
        attr_set = true;
    }

    float* h_ptr;
    cudaGetSymbolAddress((void**)&h_ptr, g_h);

    const int SCAN_BLOCKS = (NN + 1023) / 1024;  // 98

    // dtype probe + CSR build
    k_detect<<<1, 32>>>((const int*)ei);
    k_zero<<<(NN + 255) / 256, 256>>>();
    k_deg<<<(NE + 255) / 256, 256>>>(ei);
    k_scan1<<<SCAN_BLOCKS, 1024>>>();
    k_scan2<<<1, 1>>>(SCAN_BLOCKS);
    k_scan3<<<(NN + 255) / 256, 256>>>();
    k_fill<<<(NE + 255) / 256, 256>>>(ei);

    const int AGG_BLOCKS = (NN + 7) / 8;     // warp per node, 8 warps/block
    const int LIN_BLOCKS = (NN + 127) / 128;
    const size_t shbytes = SH_FLOATS * sizeof(float);

    // layer 1: x -> g_h
    k_agg<<<AGG_BLOCKS, 256>>>(x);
    k_linear<<<LIN_BLOCKS, 128, shbytes>>>(x, Wl1, bl1, Wr1, h_ptr);
    // layer 2
    k_agg<<<AGG_BLOCKS, 256>>>(h_ptr);
    k_linear<<<LIN_BLOCKS, 128, shbytes>>>(h_ptr, Wl2, bl2, Wr2, h_ptr);
    // layer 3
    k_agg<<<AGG_BLOCKS, 256>>>(h_ptr);
    k_linear<<<LIN_BLOCKS, 128, shbytes>>>(h_ptr, Wl3, bl3, Wr3, h_ptr);

    // head
    k_out<<<AGG_BLOCKS, 256>>>(h_ptr, Wout, bout, out);
}

// round 5
// speedup vs baseline: 1.3817x; 1.3817x over previous
#include <cuda_runtime.h>
#include <cuda_bf16.h>

#define NN 100000
#define NE 1600000
#define D  64

// ---------------- scratch (static device globals; no allocation) -------------
__device__ int   g_deg[NN];
__device__ int   g_fill[NN];
__device__ int   g_rowptr[NN + 1];
__device__ int   g_bsum[128];
__device__ int   g_col[NE];
__device__ float g_h[NN * D];
__device__ float g_agg[NN * D];
__device__ int   g_is64;

// ---------------- edge_index dtype detection (parallel, MLP-friendly) --------
// int64 LE with values in [0,NN): every odd int32 word is 0.
__global__ void k_detect(const int* __restrict__ w) {
    int t = threadIdx.x;                    // 32 threads
    int acc = w[2 * t + 1] | w[2 * t + 65];
    #pragma unroll
    for (int off = 16; off; off >>= 1) acc |= __shfl_xor_sync(0xffffffffu, acc, off);
    if (t == 0) g_is64 = (acc == 0) ? 1 : 0;
}

__device__ __forceinline__ int edge_at(const void* ei, long long idx) {
    if (g_is64) return (int)((const long long*)ei)[idx];
    return ((const int*)ei)[idx];
}

// ---------------- CSR construction ------------------------------------------
__global__ void k_zero() {
    int i = blockIdx.x * blockDim.x + threadIdx.x;
    if (i < NN) g_deg[i] = 0;
}

__global__ void k_deg(const void* __restrict__ ei) {
    int e = blockIdx.x * blockDim.x + threadIdx.x;
    if (e >= NE) return;
    int d = edge_at(ei, (long long)NE + e);
    if ((unsigned)d < NN) atomicAdd(&g_deg[d], 1);
}

// block-level inclusive scan (1024 elems/block), exclusive result to rowptr
__global__ void k_scan1() {
    __shared__ int sh[1024];
    int t = threadIdx.x;
    int i = blockIdx.x * 1024 + t;
    int v = (i < NN) ? g_deg[i] : 0;
    sh[t] = v;
    __syncthreads();
    #pragma unroll
    for (int off = 1; off < 1024; off <<= 1) {
        int add = (t >= off) ? sh[t - off] : 0;
        __syncthreads();
        sh[t] += add;
        __syncthreads();
    }
    if (i < NN) g_rowptr[i] = sh[t] - v;      // exclusive within block
    if (t == 1023) g_bsum[blockIdx.x] = sh[1023];
}

// parallel scan of the 98 block sums (1 block, 128 threads)
__global__ void k_scan2(int nblocks) {
    int t = threadIdx.x;
    int v = (t < nblocks) ? g_bsum[t] : 0;
    int lane = t & 31, wid = t >> 5;
    int s = v;
    #pragma unroll
    for (int off = 1; off < 32; off <<= 1) {
        int n = __shfl_up_sync(0xffffffffu, s, off);
        if (lane >= off) s += n;
    }
    __shared__ int wt[4];
    if (lane == 31) wt[wid] = s;
    __syncthreads();
    if (t == 0) {
        int r = 0;
        #pragma unroll
        for (int i = 0; i < 4; i++) { int x = wt[i]; wt[i] = r; r += x; }
    }
    __syncthreads();
    s += wt[wid];
    if (t < nblocks) g_bsum[t] = s - v;       // exclusive
    if (t == nblocks - 1) g_rowptr[NN] = s;   // total == NE
}

__global__ void k_scan3() {
    int i = blockIdx.x * blockDim.x + threadIdx.x;
    if (i < NN) {
        int r = g_rowptr[i] + g_bsum[i >> 10];
        g_rowptr[i] = r;
        g_fill[i]   = r;   // running write cursor for k_fill
    }
}

__global__ void k_fill(const void* __restrict__ ei) {
    int e = blockIdx.x * blockDim.x + threadIdx.x;
    if (e >= NE) return;
    int s = edge_at(ei, e);
    int d = edge_at(ei, (long long)NE + e);
    if ((unsigned)d >= NN || (unsigned)s >= NN) return;
    int pos = atomicAdd(&g_fill[d], 1);
    g_col[pos] = s;
}

// ---------------- mean aggregation: warp per node, float4, 2 edges/pass ------
__global__ void k_agg(const float* __restrict__ hin) {
    int node = blockIdx.x * 8 + (threadIdx.x >> 5);
    if (node >= NN) return;
    int lane = threadIdx.x & 31;
    int half = lane >> 4;          // 0/1: which edge of the pair
    int q    = lane & 15;          // float4 index within the 64-float row
    int beg = g_rowptr[node], end = g_rowptr[node + 1];
    float4 s = make_float4(0.f, 0.f, 0.f, 0.f);
    for (int e = beg + half; e < end; e += 2) {
        const float4* r = (const float4*)(hin + (size_t)g_col[e] * D);
        float4 v = r[q];
        s.x += v.x; s.y += v.y; s.z += v.z; s.w += v.w;
    }
    s.x += __shfl_xor_sync(0xffffffffu, s.x, 16);
    s.y += __shfl_xor_sync(0xffffffffu, s.y, 16);
    s.z += __shfl_xor_sync(0xffffffffu, s.z, 16);
    s.w += __shfl_xor_sync(0xffffffffu, s.w, 16);
    float inv = 1.0f / (float)max(end - beg, 1);
    if (half == 0) {
        ((float4*)(g_agg + (size_t)node * D))[q] =
            make_float4(s.x * inv, s.y * inv, s.z * inv, s.w * inv);
    }
}

// ---------------- fused dual GEMM + bias + leaky relu (+ optional head) ------
// block = 128 threads, 128 nodes x 64 outs; thread tile 8 nodes x 8 outs.
// Node indices ty+16i, out indices tx+8j -> conflict-free strided smem reads.
#define ROWP 68                               // 64 + 4 pad (16B aligned rows)
#define LIN_SMEM_FLOATS (2 * 64 * ROWP + 2 * 128 * ROWP)

__global__ __launch_bounds__(128, 2)
void k_linear(const float* __restrict__ hin,
              const float* __restrict__ Wl,
              const float* __restrict__ bl,
              const float* __restrict__ Wr,
              float* __restrict__ hout,
              const float* __restrict__ Wout,   // non-null => fused head
              const float* __restrict__ bout,
              float* __restrict__ out) {
    extern __shared__ float sh[];
    float* sWl = sh;                  // [64][ROWP]  natural [o][k]
    float* sWr = sh + 64 * ROWP;
    float* sM  = sh + 2 * 64 * ROWP;  // [128][ROWP] natural [n][k]
    float* sH  = sM + 128 * ROWP;

    int tid = threadIdx.x;
    int tx = tid & 7, ty = tid >> 3;  // tx: out group, ty: node group
    int base = blockIdx.x * 128;

    // weights: Wl[o*64+k] -> sWl[o*ROWP+k] (coalesced read, stride-1 write)
    for (int i = tid; i < 4096; i += 128) {
        int o = i >> 6, k = i & 63;
        sWl[o * ROWP + k] = Wl[i];
        sWr[o * ROWP + k] = Wr[i];
    }
    // features (agg + self), zero-padded past NN
    for (int i = tid; i < 8192; i += 128) {
        int n = i >> 6, k = i & 63;
        float m = 0.f, hv = 0.f;
        if (base + n < NN) {
            long long gi = (long long)(base + n) * D + k;
            m  = g_agg[gi];
            hv = hin[gi];
        }
        sM[n * ROWP + k] = m;
        sH[n * ROWP + k] = hv;
    }
    __syncthreads();

    float acc[64];
    #pragma unroll
    for (int j = 0; j < 8; j++) {
        float b = bl[tx + 8 * j];
        #pragma unroll
        for (int i = 0; i < 8; i++) acc[i * 8 + j] = b;
    }

    for (int kc = 0; kc < 64; kc += 4) {
        float4 m4[8], h4[8];
        #pragma unroll
        for (int i = 0; i < 8; i++) {
            m4[i] = *(const float4*)&sM[(ty + 16 * i) * ROWP + kc];
            h4[i] = *(const float4*)&sH[(ty + 16 * i) * ROWP + kc];
        }
        #pragma unroll
        for (int j = 0; j < 8; j++) {
            float4 a = *(const float4*)&sWl[(tx + 8 * j) * ROWP + kc];
            float4 b = *(const float4*)&sWr[(tx + 8 * j) * ROWP + kc];
            #pragma unroll
            for (int i = 0; i < 8; i++) {
                float v = acc[i * 8 + j];
                v = fmaf(m4[i].x, a.x, v); v = fmaf(h4[i].x, b.x, v);
                v = fmaf(m4[i].y, a.y, v); v = fmaf(h4[i].y, b.y, v);
                v = fmaf(m4[i].z, a.z, v); v = fmaf(h4[i].z, b.z, v);
                v = fmaf(m4[i].w, a.w, v); v = fmaf(h4[i].w, b.w, v);
                acc[i * 8 + j] = v;
            }
        }
    }

    // leaky relu in regs
    #pragma unroll
    for (int i = 0; i < 64; i++) {
        float v = acc[i];
        acc[i] = (v >= 0.f) ? v : 0.01f * v;
    }

    if (Wout == nullptr) {
        // write h: stage through sH for coalesced float4 stores
        __syncthreads();
        #pragma unroll
        for (int j = 0; j < 8; j++)
            #pragma unroll
            for (int i = 0; i < 8; i++)
                sH[(ty + 16 * i) * ROWP + (tx + 8 * j)] = acc[i * 8 + j];
        __syncthreads();
        for (int idx = tid; idx < 2048; idx += 128) {
            int n = idx >> 4, q = idx & 15;
            if (base + n < NN) {
                float4 v = *(const float4*)&sH[n * ROWP + q * 4];
                ((float4*)(hout + (long long)(base + n) * D))[q] = v;
            }
        }
    } else {
        // fused head: out[n] = leaky_h[n] . Wout + bout
        float wv[8];
        #pragma unroll
        for (int j = 0; j < 8; j++) wv[j] = Wout[tx + 8 * j];
        float bo = bout[0];
        #pragma unroll
        for (int i = 0; i < 8; i++) {
            float p = 0.f;
            #pragma unroll
            for (int j = 0; j < 8; j++) p = fmaf(acc[i * 8 + j], wv[j], p);
            #pragma unroll
            for (int off = 4; off; off >>= 1)
                p += __shfl_down_sync(0xffffffffu, p, off, 8);
            if (tx == 0) {
                int node = base + ty + 16 * i;
                if (node < NN) out[node] = p + bo;
            }
        }
    }
}

// ---------------- launch ------------------------------------------------------
extern "C" void kernel_launch(void* const* d_in, const int* in_sizes, int n_in,
                              void* d_out, int out_size) {
    const void*  ei   = d_in[1];
    const float* x    = (const float*)d_in[0];
    const float* Wl1  = (const float*)d_in[2];
    const float* bl1  = (const float*)d_in[3];
    const float* Wr1  = (const float*)d_in[4];
    const float* Wl2  = (const float*)d_in[5];
    const float* bl2  = (const float*)d_in[6];
    const float* Wr2  = (const float*)d_in[7];
    const float* Wl3  = (const float*)d_in[8];
    const float* bl3  = (const float*)d_in[9];
    const float* Wr3  = (const float*)d_in[10];
    const float* Wout = (const float*)d_in[11];
    const float* bout = (const float*)d_in[12];
    float* out = (float*)d_out;

    cudaFuncSetAttribute(k_linear, cudaFuncAttributeMaxDynamicSharedMemorySize,
                         LIN_SMEM_FLOATS * (int)sizeof(float));

    float* h_ptr;
    cudaGetSymbolAddress((void**)&h_ptr, g_h);

    const int SCAN_BLOCKS = (NN + 1023) / 1024;  // 98

    // dtype probe + CSR build
    k_detect<<<1, 32>>>((const int*)ei);
    k_zero<<<(NN + 255) / 256, 256>>>();
    k_deg<<<(NE + 255) / 256, 256>>>(ei);
    k_scan1<<<SCAN_BLOCKS, 1024>>>();
    k_scan2<<<1, 128>>>(SCAN_BLOCKS);
    k_scan3<<<(NN + 255) / 256, 256>>>();
    k_fill<<<(NE + 255) / 256, 256>>>(ei);

    const int AGG_BLOCKS = (NN + 7) / 8;     // warp per node, 8 warps/block
    const int LIN_BLOCKS = (NN + 127) / 128; // 782
    const size_t shbytes = LIN_SMEM_FLOATS * sizeof(float);

    // layer 1: x -> g_h
    k_agg<<<AGG_BLOCKS, 256>>>(x);
    k_linear<<<LIN_BLOCKS, 128, shbytes>>>(x, Wl1, bl1, Wr1, h_ptr,
                                           nullptr, nullptr, nullptr);
    // layer 2
    k_agg<<<AGG_BLOCKS, 256>>>(h_ptr);
    k_linear<<<LIN_BLOCKS, 128, shbytes>>>(h_ptr, Wl2, bl2, Wr2, h_ptr,
                                           nullptr, nullptr, nullptr);
    // layer 3: fused head, h never stored
    k_agg<<<AGG_BLOCKS, 256>>>(h_ptr);
    k_linear<<<LIN_BLOCKS, 128, shbytes>>>(h_ptr, Wl3, bl3, Wr3, nullptr,
                                           Wout, bout, out);
}

// round 12
// speedup vs baseline: 1.8712x; 1.3542x over previous
#include <cuda_runtime.h>
#include <cuda_bf16.h>
#include <cstdint>

#define NN 100000
#define NE 1600000
#define D  64

// ---------------- scratch (static device globals; no allocation) -------------
__device__ int   g_deg[NN];
__device__ int   g_fill[NN];
__device__ int   g_rowptr[NN + 1];
__device__ int   g_bsum[128];
__device__ int   g_col[NE];
__device__ float g_h[NN * D];
__device__ float g_agg[NN * D];
__device__ int   g_is64;
// pre-converted bf16 weight images [n=64][k=128] row-major, row stride 17 uint4
// (68 words): [layer][hi/lo][64*17]
__device__ uint4 g_wimgB[3][2][64 * 17];

// ---------------- bf16 split helper ------------------------------------------
__device__ __forceinline__ void split2(float a, float b, uint32_t& hi, uint32_t& lo) {
    __nv_bfloat162 h = __floats2bfloat162_rn(a, b);
    hi = *reinterpret_cast<uint32_t*>(&h);
    float ra = a - __low2float(h), rb = b - __high2float(h);
    __nv_bfloat162 l = __floats2bfloat162_rn(ra, rb);
    lo = *reinterpret_cast<uint32_t*>(&l);
}

// ---------------- edge_index dtype detection ---------------------------------
__global__ void k_detect(const int* __restrict__ w) {
    int t = threadIdx.x;
    int acc = w[2 * t + 1] | w[2 * t + 65];
    #pragma unroll
    for (int off = 16; off; off >>= 1) acc |= __shfl_xor_sync(0xffffffffu, acc, off);
    if (t == 0) g_is64 = (acc == 0) ? 1 : 0;
}
__device__ __forceinline__ int edge_at(const void* ei, long long idx) {
    if (g_is64) return (int)((const long long*)ei)[idx];
    return ((const int*)ei)[idx];
}

// ---------------- CSR construction ------------------------------------------
__global__ void k_zero() {
    int i = blockIdx.x * blockDim.x + threadIdx.x;
    if (i < NN) g_deg[i] = 0;
}
__global__ void k_deg(const void* __restrict__ ei) {
    int e = blockIdx.x * blockDim.x + threadIdx.x;
    if (e >= NE) return;
    int d = edge_at(ei, (long long)NE + e);
    if ((unsigned)d < NN) atomicAdd(&g_deg[d], 1);
}
__global__ void k_scan1() {
    __shared__ int sh[1024];
    int t = threadIdx.x;
    int i = blockIdx.x * 1024 + t;
    int v = (i < NN) ? g_deg[i] : 0;
    sh[t] = v;
    __syncthreads();
    #pragma unroll
    for (int off = 1; off < 1024; off <<= 1) {
        int add = (t >= off) ? sh[t - off] : 0;
        __syncthreads();
        sh[t] += add;
        __syncthreads();
    }
    if (i < NN) g_rowptr[i] = sh[t] - v;
    if (t == 1023) g_bsum[blockIdx.x] = sh[1023];
}
__global__ void k_scan2(int nblocks) {
    int t = threadIdx.x;
    int v = (t < nblocks) ? g_bsum[t] : 0;
    int lane = t & 31, wid = t >> 5;
    int s = v;
    #pragma unroll
    for (int off = 1; off < 32; off <<= 1) {
        int n = __shfl_up_sync(0xffffffffu, s, off);
        if (lane >= off) s += n;
    }
    __shared__ int wt[4];
    if (lane == 31) wt[wid] = s;
    __syncthreads();
    if (t == 0) {
        int r = 0;
        #pragma unroll
        for (int i = 0; i < 4; i++) { int x = wt[i]; wt[i] = r; r += x; }
    }
    __syncthreads();
    s += wt[wid];
    if (t < nblocks) g_bsum[t] = s - v;
    if (t == nblocks - 1) g_rowptr[NN] = s;
}
__global__ void k_scan3() {
    int i = blockIdx.x * blockDim.x + threadIdx.x;
    if (i < NN) {
        int r = g_rowptr[i] + g_bsum[i >> 10];
        g_rowptr[i] = r;
        g_fill[i]   = r;
    }
}
__global__ void k_fill(const void* __restrict__ ei) {
    int e = blockIdx.x * blockDim.x + threadIdx.x;
    if (e >= NE) return;
    int s = edge_at(ei, e);
    int d = edge_at(ei, (long long)NE + e);
    if ((unsigned)d >= NN || (unsigned)s >= NN) return;
    int pos = atomicAdd(&g_fill[d], 1);
    g_col[pos] = s;
}

// ---------------- mean aggregation: warp per node, float4, unrolled ----------
__global__ void k_agg(const float* __restrict__ hin) {
    int node = blockIdx.x * 8 + (threadIdx.x >> 5);
    if (node >= NN) return;
    int lane = threadIdx.x & 31;
    int half = lane >> 4;
    int q    = lane & 15;
    int beg = g_rowptr[node], end = g_rowptr[node + 1];
    float4 s0 = make_float4(0.f, 0.f, 0.f, 0.f);
    float4 s1 = make_float4(0.f, 0.f, 0.f, 0.f);
    int e = beg + half;
    for (; e + 2 < end; e += 4) {
        const float4* r0 = (const float4*)(hin + (size_t)g_col[e] * D);
        const float4* r1 = (const float4*)(hin + (size_t)g_col[e + 2] * D);
        float4 v0 = r0[q], v1 = r1[q];
        s0.x += v0.x; s0.y += v0.y; s0.z += v0.z; s0.w += v0.w;
        s1.x += v1.x; s1.y += v1.y; s1.z += v1.z; s1.w += v1.w;
    }
    if (e < end) {
        const float4* r0 = (const float4*)(hin + (size_t)g_col[e] * D);
        float4 v0 = r0[q];
        s0.x += v0.x; s0.y += v0.y; s0.z += v0.z; s0.w += v0.w;
    }
    s0.x += s1.x; s0.y += s1.y; s0.z += s1.z; s0.w += s1.w;
    s0.x += __shfl_xor_sync(0xffffffffu, s0.x, 16);
    s0.y += __shfl_xor_sync(0xffffffffu, s0.y, 16);
    s0.z += __shfl_xor_sync(0xffffffffu, s0.z, 16);
    s0.w += __shfl_xor_sync(0xffffffffu, s0.w, 16);
    float inv = 1.0f / (float)max(end - beg, 1);
    if (half == 0) {
        ((float4*)(g_agg + (size_t)node * D))[q] =
            make_float4(s0.x * inv, s0.y * inv, s0.z * inv, s0.w * inv);
    }
}

// ---------------- weight convert: fp32 -> bf16 hi/lo images -------------------
// B[n][k]: k<64 -> Wl[n][k], k>=64 -> Wr[n][k-64]; row stride 17 uint4.
__global__ void k_wconv(const float* __restrict__ Wl, const float* __restrict__ Wr,
                        int layer) {
    int c = blockIdx.x * blockDim.x + threadIdx.x;   // 1024 = 64 rows x 16 k8
    if (c >= 1024) return;
    int n = c >> 4, k8 = c & 15;
    const float* src = (k8 < 8) ? (Wl + n * 64 + k8 * 8)
                                : (Wr + n * 64 + (k8 - 8) * 8);
    float4 p0 = *(const float4*)src;
    float4 p1 = *(const float4*)(src + 4);
    uint4 hi, lo;
    split2(p0.x, p0.y, hi.x, lo.x);
    split2(p0.z, p0.w, hi.y, lo.y);
    split2(p1.x, p1.y, hi.z, lo.z);
    split2(p1.z, p1.w, hi.w, lo.w);
    g_wimgB[layer][0][n * 17 + k8] = hi;
    g_wimgB[layer][1][n * 17 + k8] = lo;
}

// ---------------- HMMA dual-GEMM + bias + leaky relu (+ optional head) -------
// A = [mean | h] 128x128 (row stride 68 words), B = [Wl | Wr] 64x128.
// acc = A_hi B_hi^T + A_hi B_lo^T + A_lo B_hi^T  (fp32, mma.sync m16n8k16 bf16)
#define AHI_W 0
#define ALO_W 8704                 // 128*68
#define BHI_W 17408
#define BLO_W 21760                // +64*68
#define SMEM_WORDS 26112           // 104448 bytes
#define STG_STRIDE 68

#define MMA(acc, a0, a1, a2, a3, b0, b1)                                    \
    asm volatile("mma.sync.aligned.m16n8k16.row.col.f32.bf16.bf16.f32 "     \
                 "{%0,%1,%2,%3}, {%4,%5,%6,%7}, {%8,%9}, {%0,%1,%2,%3};"    \
                 : "+f"((acc)[0]), "+f"((acc)[1]), "+f"((acc)[2]), "+f"((acc)[3]) \
                 : "r"(a0), "r"(a1), "r"(a2), "r"(a3), "r"(b0), "r"(b1))

__global__ __launch_bounds__(256, 2)
void k_linear(const float* __restrict__ hin, int layer,
              const float* __restrict__ bl,
              float* __restrict__ hout,
              const float* __restrict__ Wout,
              const float* __restrict__ bout,
              float* __restrict__ out) {
    extern __shared__ uint32_t sw[];
    int tid = threadIdx.x;
    int wid = tid >> 5, lane = tid & 31;
    int g = lane >> 2, q = lane & 3;
    int base = blockIdx.x * 128;

    // B images: 1088 uint4 per plane
    {
        const uint4* wh = g_wimgB[layer][0];
        const uint4* wl = g_wimgB[layer][1];
        uint4* dh = (uint4*)(sw + BHI_W);
        uint4* dl = (uint4*)(sw + BLO_W);
        for (int i = tid; i < 1088; i += 256) { dh[i] = wh[i]; dl[i] = wl[i]; }
    }
    // A = [mean | h]: 2048 chunks of 8 floats -> bf16 hi/lo
    for (int c = tid; c < 2048; c += 256) {
        int row = c >> 4, k8 = c & 15;
        int node = base + row;
        uint4 hi = make_uint4(0, 0, 0, 0), lo = make_uint4(0, 0, 0, 0);
        if (node < NN) {
            const float* src = (k8 < 8) ? (g_agg + (size_t)node * 64 + k8 * 8)
                                        : (hin + (size_t)node * 64 + (k8 - 8) * 8);
            float4 p0 = *(const float4*)src;
            float4 p1 = *(const float4*)(src + 4);
            split2(p0.x, p0.y, hi.x, lo.x);
            split2(p0.z, p0.w, hi.y, lo.y);
            split2(p1.x, p1.y, hi.z, lo.z);
            split2(p1.z, p1.w, hi.w, lo.w);
        }
        int w = row * 68 + k8 * 4;
        *(uint4*)(sw + AHI_W + w) = hi;
        *(uint4*)(sw + ALO_W + w) = lo;
    }
    __syncthreads();

    // accumulators: 8 n-tiles x {c0,c1,c2,c3}; init with bias
    float acc[8][4];
    #pragma unroll
    for (int j = 0; j < 8; j++) {
        float2 b2 = *(const float2*)(bl + j * 8 + q * 2);
        acc[j][0] = b2.x; acc[j][1] = b2.y;
        acc[j][2] = b2.x; acc[j][3] = b2.y;
    }

    int wrow = wid * 16;
    const uint32_t* Ah = sw + AHI_W;
    const uint32_t* Al = sw + ALO_W;
    const uint32_t* Bh = sw + BHI_W;
    const uint32_t* Bl = sw + BLO_W;
    int ar0 = (wrow + g) * 68, ar1 = (wrow + g + 8) * 68;

    #pragma unroll
    for (int s = 0; s < 8; s++) {
        int ka = s * 8 + q;
        uint32_t ah0 = Ah[ar0 + ka],     ah1 = Ah[ar1 + ka];
        uint32_t ah2 = Ah[ar0 + ka + 4], ah3 = Ah[ar1 + ka + 4];
        uint32_t al0 = Al[ar0 + ka],     al1 = Al[ar1 + ka];
        uint32_t al2 = Al[ar0 + ka + 4], al3 = Al[ar1 + ka + 4];
        #pragma unroll
        for (int j = 0; j < 8; j++) {
            int br = (j * 8 + g) * 68 + s * 8 + q;
            uint32_t bh0 = Bh[br], bh1 = Bh[br + 4];
            uint32_t bl0 = Bl[br], bl1 = Bl[br + 4];
            MMA(acc[j], ah0, ah1, ah2, ah3, bh0, bh1);
            MMA(acc[j], ah0, ah1, ah2, ah3, bl0, bl1);
            MMA(acc[j], al0, al1, al2, al3, bh0, bh1);
        }
    }

    // leaky relu
    #pragma unroll
    for (int j = 0; j < 8; j++)
        #pragma unroll
        for (int c = 0; c < 4; c++) {
            float v = acc[j][c];
            acc[j][c] = (v >= 0.f) ? v : 0.01f * v;
        }

    if (Wout == nullptr) {
        // stage to smem [128][68], then coalesced float4 stores
        __syncthreads();
        float* stg = (float*)sw;
        #pragma unroll
        for (int j = 0; j < 8; j++) {
            int col = j * 8 + q * 2;
            *(float2*)(stg + (wrow + g) * STG_STRIDE + col)     = make_float2(acc[j][0], acc[j][1]);
            *(float2*)(stg + (wrow + g + 8) * STG_STRIDE + col) = make_float2(acc[j][2], acc[j][3]);
        }
        __syncthreads();
        for (int idx = tid; idx < 2048; idx += 256) {
            int r = idx >> 4, q4 = idx & 15;
            int node = base + r;
            if (node < NN) {
                float4 v = *(const float4*)(stg + r * STG_STRIDE + q4 * 4);
                ((float4*)(hout + (size_t)node * 64))[q4] = v;
            }
        }
    } else {
        // fused head: each thread holds cols {j*8+q*2, +1} of rows wrow+g, wrow+g+8
        float p0 = 0.f, p1 = 0.f;
        #pragma unroll
        for (int j = 0; j < 8; j++) {
            float2 w2 = *(const float2*)(Wout + j * 8 + q * 2);
            p0 = fmaf(acc[j][0], w2.x, p0); p0 = fmaf(acc[j][1], w2.y, p0);
            p1 = fmaf(acc[j][2], w2.x, p1); p1 = fmaf(acc[j][3], w2.y, p1);
        }
        // reduce across the 4 q-threads (lanes g*4+q)
        #pragma unroll
        for (int off = 1; off < 4; off <<= 1) {
            p0 += __shfl_xor_sync(0xffffffffu, p0, off);
            p1 += __shfl_xor_sync(0xffffffffu, p1, off);
        }
        if (q == 0) {
            float bo = bout[0];
            int n0 = base + wrow + g, n1 = n0 + 8;
            if (n0 < NN) out[n0] = p0 + bo;
            if (n1 < NN) out[n1] = p1 + bo;
        }
    }
}

// ---------------- launch ------------------------------------------------------
extern "C" void kernel_launch(void* const* d_in, const int* in_sizes, int n_in,
                              void* d_out, int out_size) {
    const void*  ei   = d_in[1];
    const float* x    = (const float*)d_in[0];
    const float* Wl1  = (const float*)d_in[2];
    const float* bl1  = (const float*)d_in[3];
    const float* Wr1  = (const float*)d_in[4];
    const float* Wl2  = (const float*)d_in[5];
    const float* bl2  = (const float*)d_in[6];
    const float* Wr2  = (const float*)d_in[7];
    const float* Wl3  = (const float*)d_in[8];
    const float* bl3  = (const float*)d_in[9];
    const float* Wr3  = (const float*)d_in[10];
    const float* Wout = (const float*)d_in[11];
    const float* bout = (const float*)d_in[12];
    float* out = (float*)d_out;

    cudaFuncSetAttribute(k_linear, cudaFuncAttributeMaxDynamicSharedMemorySize,
                         SMEM_WORDS * 4);

    float* h_ptr;
    cudaGetSymbolAddress((void**)&h_ptr, g_h);

    const int SCAN_BLOCKS = (NN + 1023) / 1024;  // 98

    // dtype probe + CSR build
    k_detect<<<1, 32>>>((const int*)ei);
    k_zero<<<(NN + 255) / 256, 256>>>();
    k_deg<<<(NE + 255) / 256, 256>>>(ei);
    k_scan1<<<SCAN_BLOCKS, 1024>>>();
    k_scan2<<<1, 128>>>(SCAN_BLOCKS);
    k_scan3<<<(NN + 255) / 256, 256>>>();
    k_fill<<<(NE + 255) / 256, 256>>>(ei);

    // weight conversion (hi/lo split images)
    k_wconv<<<8, 128>>>(Wl1, Wr1, 0);
    k_wconv<<<8, 128>>>(Wl2, Wr2, 1);
    k_wconv<<<8, 128>>>(Wl3, Wr3, 2);

    const int AGG_BLOCKS = (NN + 7) / 8;
    const int LIN_BLOCKS = (NN + 127) / 128;   // 782
    const size_t shb = SMEM_WORDS * 4;

    // layer 1: x -> g_h
    k_agg<<<AGG_BLOCKS, 256>>>(x);
    k_linear<<<LIN_BLOCKS, 256, shb>>>(x, 0, bl1, h_ptr, nullptr, nullptr, nullptr);
    // layer 2
    k_agg<<<AGG_BLOCKS, 256>>>(h_ptr);
    k_linear<<<LIN_BLOCKS, 256, shb>>>(h_ptr, 1, bl2, h_ptr, nullptr, nullptr, nullptr);
    // layer 3: fused head
    k_agg<<<AGG_BLOCKS, 256>>>(h_ptr);
    k_linear<<<LIN_BLOCKS, 256, shb>>>(h_ptr, 2, bl3, nullptr, Wout, bout, out);
}